// round 16
// baseline (speedup 1.0000x reference)
#include <cuda_runtime.h>
#include <cuda_bf16.h>
#include <math.h>
#include <stdint.h>

// ============================================================================
// DecoderAttention via HMMA (mma.sync bf16, 3-term hi/lo split, fp32 accum).
// Universal NT GEMM: D[M,N] = sum_k A[m,k]*B[n,k], A/B as bf16 (hi,lo) planes.
// R15: CTA tile 128x64 (warp 64x16), occupancy 3 (<=85 regs), 6 warps/SMSP,
//      3-stage 24K cp.async pipeline; all grids double.
// ============================================================================

#define HID 1024
#define SQ 512
#define SE 1024
#define NB 4
#define VOCAB_N 32000
#define MQ (NB*SQ)    // 2048
#define ME (NB*SE)    // 4096
#define HH (HID*HID)

typedef __nv_bfloat16 bf16;

// ---------------- device scratch (static; no runtime allocation) ------------
__device__ bf16 g_wh[6*HH + (size_t)HID*VOCAB_N];
__device__ bf16 g_wl[6*HH + (size_t)HID*VOCAB_N];
__device__ bf16 g_xh[MQ*HID],  g_xl[MQ*HID];
__device__ bf16 g_qkh[(MQ+ME)*HID], g_qkl[(MQ+ME)*HID];  // Q rows then K rows
__device__ bf16 g_vth[ME*HID], g_vtl[ME*HID];   // V^T planes
__device__ bf16 g_ah[MQ*HID],  g_al[MQ*HID];
__device__ bf16 g_ch[MQ*HID],  g_cl[MQ*HID];
__device__ bf16 g_eh[ME*HID],  g_el[ME*HID];
__device__ float g_s[MQ*SE];
__device__ bf16 g_ph[MQ*SE],   g_pl[MQ*SE];
__device__ float g_bias[2*HID];                  // staged bq_s | bk_s

// ---------------- helpers ----------------------------------------------------
__device__ __forceinline__ uint32_t smem_u32(const void* p) {
    uint32_t a;
    asm("{ .reg .u64 t; cvta.to.shared.u64 t, %1; cvt.u32.u64 %0, t; }" : "=r"(a) : "l"(p));
    return a;
}
__device__ __forceinline__ uint32_t pack2(bf16 a, bf16 b) {
    return (uint32_t)__bfloat16_as_ushort(a) | ((uint32_t)__bfloat16_as_ushort(b) << 16);
}
__device__ __forceinline__ void split1(float v, bf16& h, bf16& l) {
    h = __float2bfloat16(v);
    l = __float2bfloat16(v - __bfloat162float(h));
}
__device__ __forceinline__ void cpa16(uint32_t dst, const void* src) {
    asm volatile("{ .reg .u64 g; cvta.to.global.u64 g, %1; cp.async.cg.shared.global [%0], [g], 16; }"
                 :: "r"(dst), "l"(src));
}
__device__ __forceinline__ void cpa_commit() { asm volatile("cp.async.commit_group;" ::: "memory"); }
__device__ __forceinline__ void cpa_wait1()  { asm volatile("cp.async.wait_group 1;" ::: "memory"); }

__device__ __forceinline__ void ldsm4(uint32_t* r, uint32_t addr) {
    asm volatile("ldmatrix.sync.aligned.m8n8.x4.shared.b16 {%0,%1,%2,%3}, [%4];"
                 : "=r"(r[0]), "=r"(r[1]), "=r"(r[2]), "=r"(r[3]) : "r"(addr));
}
__device__ __forceinline__ void mma_bf16(float* c, const uint32_t* a, const uint32_t* b) {
    asm volatile(
        "mma.sync.aligned.m16n8k16.row.col.f32.bf16.bf16.f32 "
        "{%0,%1,%2,%3}, {%4,%5,%6,%7}, {%8,%9}, {%0,%1,%2,%3};"
        : "+f"(c[0]), "+f"(c[1]), "+f"(c[2]), "+f"(c[3])
        : "r"(a[0]), "r"(a[1]), "r"(a[2]), "r"(a[3]), "r"(b[0]), "r"(b[1]));
}

// XOR swizzle for 64B rows (32 bf16): unit' = ((r&1)*4+sg) ^ ((r>>1)&7)
__device__ __forceinline__ uint32_t swo(int r, int sg) {
    return (uint32_t)(((r >> 1) << 7) | ((((((r & 1) << 2) | sg)) ^ ((r >> 1) & 7)) << 4));
}

// ---------------- main GEMM --------------------------------------------------
// Tile 128(M) x 64(N), BK=32, 256 threads = 8 warps (2m x 4n), warp 64x16.
// Stage: Ah 8K | Al 8K | Bh 4K | Bl 4K = 24K. 3 stages = 72K smem. occ 3.
#define STG 24576
#define SMEM_TOT (3*STG)
#define OF_AL 8192
#define OF_BH 16384
#define OF_BL 20480

__device__ __forceinline__ void fill_stage(uint32_t s, const bf16* ah, const bf16* al,
                                           const bf16* bh, const bf16* bl,
                                           int lda, int ldb, int k0, int tid) {
    int r = tid >> 2, sg = tid & 3;                 // r: 0..63
    uint32_t o = swo(r, sg);
    size_t ga = (size_t)r * lda + k0 + sg * 8;      // A rows r and r+64
    cpa16(s + o,               ah + ga);
    cpa16(s + OF_AL + o,       al + ga);
    size_t ga2 = ga + (size_t)64 * lda;             // swo(r+64,sg) = o + 4096
    cpa16(s + o + 4096,        ah + ga2);
    cpa16(s + OF_AL + o + 4096, al + ga2);
    size_t gb = (size_t)r * ldb + k0 + sg * 8;      // B rows 0..63
    cpa16(s + OF_BH + o, bh + gb);
    cpa16(s + OF_BL + o, bl + gb);
}

__global__ __launch_bounds__(256, 3)
void gemm3(const bf16* __restrict__ Ah, const bf16* __restrict__ Al, int lda, long long zsA,
           const bf16* __restrict__ Bh, const bf16* __restrict__ Bl, int ldb, long long zsB,
           float* __restrict__ Cf, bf16* __restrict__ Ch, bf16* __restrict__ Cl,
           int ldc, long long zsC,
           int K, const float* __restrict__ bias, long long zsBias, int bmode, int kmode) {
    extern __shared__ __align__(128) char smem[];
    int row0 = blockIdx.x * 128, col0 = blockIdx.y * 64;
    if (kmode == 1 && col0 > row0 + 127) return;     // causal scores: above diag
    int Ke = (kmode == 2 && K > row0 + 128) ? (row0 + 128) : K;

    uint32_t sb = smem_u32(smem);
    int tid = threadIdx.x, lane = tid & 31, wid = tid >> 5;
    int wm = wid & 1, wn = wid >> 1;                  // 2m x 4n warps (64x16 tiles)
    long long z = blockIdx.z;
    const bf16* a_h = Ah + z * zsA + (size_t)row0 * lda;
    const bf16* a_l = Al + z * zsA + (size_t)row0 * lda;
    const bf16* b_h = Bh + z * zsB + (size_t)col0 * ldb;
    const bf16* b_l = Bl + z * zsB + (size_t)col0 * ldb;

    float acc[4][2][4] = {};
    int NC = Ke >> 5;

    #pragma unroll
    for (int p = 0; p < 2; p++) {
        if (p < NC) fill_stage(sb + (uint32_t)p * STG, a_h, a_l, b_h, b_l, lda, ldb, p << 5, tid);
        cpa_commit();
    }

    // per-lane ldmatrix base offsets
    int lr = lane & 15, lc = lane >> 4;
    int rA = wm * 64 + lr;
    uint32_t aoff[2] = { swo(rA, lc), swo(rA, 2 + lc) };
    int rB = wn * 16 + ((lane >> 4) << 3) + (lane & 7);
    int sg0 = (lane >> 3) & 1;
    uint32_t boff[2] = { OF_BH + swo(rB, sg0), OF_BH + swo(rB, 2 + sg0) };

    int sidx = 0;
    for (int c = 0; c < NC; c++) {
        cpa_wait1();
        __syncthreads();
        int f = c + 2;
        int fidx = sidx + 2; if (fidx >= 3) fidx -= 3;
        if (f < NC)
            fill_stage(sb + (uint32_t)fidx * STG, a_h, a_l, b_h, b_l, lda, ldb, f << 5, tid);
        cpa_commit();

        uint32_t s = sb + (uint32_t)sidx * STG;
        #pragma unroll
        for (int ks = 0; ks < 2; ks++) {
            uint32_t ao = s + aoff[ks];
            uint32_t bo = s + boff[ks];
            uint32_t bh4[4], bl4[4];
            ldsm4(bh4, bo);
            ldsm4(bl4, bo + 4096u);
            #pragma unroll
            for (int i = 0; i < 4; i++) {
                uint32_t aH[4], aL[4];
                ldsm4(aH, ao + (uint32_t)(i * 1024));
                ldsm4(aL, ao + 8192u + (uint32_t)(i * 1024));
                mma_bf16(acc[i][0], aH, &bh4[0]);
                mma_bf16(acc[i][1], aH, &bh4[2]);
                mma_bf16(acc[i][0], aH, &bl4[0]);
                mma_bf16(acc[i][1], aH, &bl4[2]);
                mma_bf16(acc[i][0], aL, &bh4[0]);
                mma_bf16(acc[i][1], aL, &bh4[2]);
            }
        }
        if (++sidx == 3) sidx = 0;
    }

    // ---- epilogue ----
    size_t zoff = (size_t)z * (size_t)zsC;
    const float* bz = bias + (size_t)z * (size_t)zsBias;
    int gr = row0 + wm * 64;
    int gc = col0 + wn * 16;
    int rr = lane >> 2, cc = (lane & 3) * 2;

    #pragma unroll
    for (int i = 0; i < 4; i++) {
        #pragma unroll
        for (int j = 0; j < 2; j++) {
            int r0g = gr + i * 16 + rr;
            int c0g = gc + j * 8 + cc;
            float v0 = acc[i][j][0], v1 = acc[i][j][1];
            float v2 = acc[i][j][2], v3 = acc[i][j][3];
            if (bmode == 1) {
                float b0 = bz[c0g], b1 = bz[c0g + 1];
                v0 += b0; v1 += b1; v2 += b0; v3 += b1;
            } else if (bmode == 2) {
                float br0 = bz[r0g], br1 = bz[r0g + 8];
                v0 += br0; v1 += br0; v2 += br1; v3 += br1;
            }
            size_t o0 = zoff + (size_t)r0g * ldc + c0g;
            size_t o1 = zoff + (size_t)(r0g + 8) * ldc + c0g;
            if (Cf) {
                *(float2*)(Cf + o0) = make_float2(v0, v1);
                *(float2*)(Cf + o1) = make_float2(v2, v3);
            } else {
                bf16 h0, l0, h1, l1;
                split1(v0, h0, l0); split1(v1, h1, l1);
                *(uint32_t*)(Ch + o0) = pack2(h0, h1);
                *(uint32_t*)(Cl + o0) = pack2(l0, l1);
                split1(v2, h0, l0); split1(v3, h1, l1);
                *(uint32_t*)(Ch + o1) = pack2(h0, h1);
                *(uint32_t*)(Cl + o1) = pack2(l0, l1);
            }
        }
    }
}

// ---------------- prep: fast coalesced weight transpose ----------------------
__global__ __launch_bounds__(256)
void prep_wT(const float* __restrict__ W0, const float* __restrict__ W1,
             const float* __restrict__ W2, const float* __restrict__ W3,
             const float* __restrict__ W4, const float* __restrict__ W5,
             const float* __restrict__ W6,
             bf16* __restrict__ Th, bf16* __restrict__ Tl) {
    const float* Ws[6] = {W0, W1, W2, W3, W4, W5};
    __shared__ float t[128][33];
    int bid = blockIdx.x, tid = threadIdx.x;
    const float* W; bf16 *th, *tl; int n0, k0, N;
    if (bid < 1536) {
        int w = bid >> 8, tt = bid & 255;
        W = Ws[w]; th = Th + (size_t)w * HH; tl = Tl + (size_t)w * HH;
        k0 = (tt >> 5) * 128; n0 = (tt & 31) * 32; N = HID;
    } else {
        int tt = bid - 1536;
        W = W6; th = Th + (size_t)6 * HH; tl = Tl + (size_t)6 * HH;
        n0 = (tt % 1000) * 32; k0 = (tt / 1000) * 128; N = VOCAB_N;
    }
    int r0 = tid >> 3, c4 = tid & 7;
    #pragma unroll
    for (int i = 0; i < 4; i++) {
        int r = r0 + i * 32;
        float4 v = *(const float4*)(W + (size_t)(k0 + r) * N + n0 + c4 * 4);
        t[r][c4 * 4 + 0] = v.x;
        t[r][c4 * 4 + 1] = v.y;
        t[r][c4 * 4 + 2] = v.z;
        t[r][c4 * 4 + 3] = v.w;
    }
    __syncthreads();
    int c = tid >> 3, seg = tid & 7;
    uint32_t hp[8], lp[8];
    #pragma unroll
    for (int u = 0; u < 8; u++) {
        float v0 = t[seg * 16 + u * 2][c];
        float v1 = t[seg * 16 + u * 2 + 1][c];
        bf16 h0, l0, h1, l1;
        split1(v0, h0, l0); split1(v1, h1, l1);
        hp[u] = pack2(h0, h1);
        lp[u] = pack2(l0, l1);
    }
    size_t o = (size_t)(n0 + c) * HID + k0 + seg * 16;
    *(uint4*)(th + o)     = make_uint4(hp[0], hp[1], hp[2], hp[3]);
    *(uint4*)(th + o + 8) = make_uint4(hp[4], hp[5], hp[6], hp[7]);
    *(uint4*)(tl + o)     = make_uint4(lp[0], lp[1], lp[2], lp[3]);
    *(uint4*)(tl + o + 8) = make_uint4(lp[4], lp[5], lp[6], lp[7]);
}

// ---------------- prep: encoder split + embedding + bias staging -------------
__global__ void prep_act(const float* __restrict__ enc,
                         const int* __restrict__ tok,
                         const float* __restrict__ temb,
                         const float* __restrict__ pemb,
                         const float* __restrict__ bq, const float* __restrict__ bk,
                         bf16* __restrict__ eh, bf16* __restrict__ el,
                         bf16* __restrict__ xh, bf16* __restrict__ xl,
                         float* __restrict__ biasbuf) {
    int bid = blockIdx.x;
    int i = threadIdx.x;  // 0..255
    if (bid < ME) {
        const float4* src = (const float4*)(enc + (size_t)bid * HID);
        float4 v = src[i];
        bf16 h0,l0,h1,l1,h2,l2,h3,l3;
        split1(v.x,h0,l0); split1(v.y,h1,l1); split1(v.z,h2,l2); split1(v.w,h3,l3);
        ((uint2*)(eh + (size_t)bid * HID))[i] = make_uint2(pack2(h0,h1), pack2(h2,h3));
        ((uint2*)(el + (size_t)bid * HID))[i] = make_uint2(pack2(l0,l1), pack2(l2,l3));
    } else if (bid < ME + MQ) {
        int bs = bid - ME;
        int s = bs & (SQ - 1);
        int t = tok[bs];
        const float4* te = (const float4*)(temb + (size_t)t * HID);
        const float4* pe = (const float4*)(pemb + (size_t)s * HID);
        float4 a = te[i], b = pe[i];
        bf16 h0,l0,h1,l1,h2,l2,h3,l3;
        split1(a.x+b.x,h0,l0); split1(a.y+b.y,h1,l1);
        split1(a.z+b.z,h2,l2); split1(a.w+b.w,h3,l3);
        ((uint2*)(xh + (size_t)bs * HID))[i] = make_uint2(pack2(h0,h1), pack2(h2,h3));
        ((uint2*)(xl + (size_t)bs * HID))[i] = make_uint2(pack2(l0,l1), pack2(l2,l3));
    } else {
        ((float4*)biasbuf)[i]         = ((const float4*)bq)[i];
        ((float4*)(biasbuf + HID))[i] = ((const float4*)bk)[i];
    }
}

// ---------------- softmax ----------------------------------------------------
__device__ __forceinline__ float warpMaxf(float v) {
    #pragma unroll
    for (int o = 16; o > 0; o >>= 1) v = fmaxf(v, __shfl_xor_sync(0xffffffffu, v, o));
    return v;
}
__device__ __forceinline__ float warpSumf(float v) {
    #pragma unroll
    for (int o = 16; o > 0; o >>= 1) v += __shfl_xor_sync(0xffffffffu, v, o);
    return v;
}

__global__ void softmax_split(const float* __restrict__ S,
                              bf16* __restrict__ Ph, bf16* __restrict__ Pl,
                              int L, int causal) {
    __shared__ float e[SE];
    __shared__ float shm[8], shs[8];
    __shared__ float bmax, bsum;
    int row = blockIdx.x;
    int q = row & (SQ - 1);
    const float* s = S + (size_t)row * L;
    int valid = causal ? (q + 1) : L;
    int tid = threadIdx.x, lane = tid & 31, w = tid >> 5;

    float m = -1e30f;
    for (int k = tid; k < valid; k += 256) m = fmaxf(m, s[k]);
    m = warpMaxf(m);
    if (lane == 0) shm[w] = m;
    __syncthreads();
    if (w == 0) {
        float x = (lane < 8) ? shm[lane] : -1e30f;
        x = warpMaxf(x);
        if (lane == 0) bmax = x;
    }
    __syncthreads();
    m = bmax;

    float sum = 0.f;
    for (int k = tid; k < valid; k += 256) {
        float ex = expf((s[k] - m) * 0.03125f);
        e[k] = ex;
        sum += ex;
    }
    sum = warpSumf(sum);
    if (lane == 0) shs[w] = sum;
    __syncthreads();
    if (w == 0) {
        float x = (lane < 8) ? shs[lane] : 0.f;
        x = warpSumf(x);
        if (lane == 0) bsum = x;
    }
    __syncthreads();
    float inv = 1.f / bsum;

    size_t o = (size_t)row * L;
    for (int k = tid; k < L; k += 256) {
        float p = (k < valid) ? e[k] * inv : 0.f;
        bf16 h, l; split1(p, h, l);
        Ph[o + k] = h;
        Pl[o + k] = l;
    }
}

// ---------------- launch -----------------------------------------------------
extern "C" void kernel_launch(void* const* d_in, const int* in_sizes, int n_in,
                              void* d_out, int out_size) {
    const float* enc   = (const float*)d_in[0];
    const int*   tok   = (const int*)d_in[1];
    const float* temb  = (const float*)d_in[2];
    const float* pemb  = (const float*)d_in[3];
    const float* Wq_s  = (const float*)d_in[4];
    const float* bq_s  = (const float*)d_in[5];
    const float* Wk_s  = (const float*)d_in[6];
    const float* bk_s  = (const float*)d_in[7];
    const float* Wv_s  = (const float*)d_in[8];
    const float* bv_s  = (const float*)d_in[9];
    const float* Wq_c  = (const float*)d_in[10];
    const float* bq_c  = (const float*)d_in[11];
    const float* Wk_c  = (const float*)d_in[12];
    const float* bk_c  = (const float*)d_in[13];
    const float* Wv_c  = (const float*)d_in[14];
    const float* bv_c  = (const float*)d_in[15];
    const float* Wout  = (const float*)d_in[16];
    const float* bout  = (const float*)d_in[17];
    float* out = (float*)d_out;

    cudaFuncSetAttribute(gemm3, cudaFuncAttributeMaxDynamicSharedMemorySize, SMEM_TOT);

    bf16 *wh, *wl, *xh, *xl, *qkh, *qkl, *vth, *vtl, *ah, *al, *ch, *cl, *eh, *el, *ph, *pl;
    float *s, *bb;
    cudaGetSymbolAddress((void**)&wh, g_wh);   cudaGetSymbolAddress((void**)&wl, g_wl);
    cudaGetSymbolAddress((void**)&xh, g_xh);   cudaGetSymbolAddress((void**)&xl, g_xl);
    cudaGetSymbolAddress((void**)&qkh, g_qkh); cudaGetSymbolAddress((void**)&qkl, g_qkl);
    cudaGetSymbolAddress((void**)&vth, g_vth); cudaGetSymbolAddress((void**)&vtl, g_vtl);
    cudaGetSymbolAddress((void**)&ah, g_ah);   cudaGetSymbolAddress((void**)&al, g_al);
    cudaGetSymbolAddress((void**)&ch, g_ch);   cudaGetSymbolAddress((void**)&cl, g_cl);
    cudaGetSymbolAddress((void**)&eh, g_eh);   cudaGetSymbolAddress((void**)&el, g_el);
    cudaGetSymbolAddress((void**)&ph, g_ph);   cudaGetSymbolAddress((void**)&pl, g_pl);
    cudaGetSymbolAddress((void**)&s, g_s);     cudaGetSymbolAddress((void**)&bb, g_bias);

    bf16* kh = qkh + (size_t)MQ * HID;   // K region (ME capacity)
    bf16* kl = qkl + (size_t)MQ * HID;

    prep_wT<<<9536, 256>>>(Wq_s, Wk_s, Wv_s, Wq_c, Wk_c, Wv_c, Wout, wh, wl);
    prep_act<<<ME + MQ + 1, 256>>>(enc, tok, temb, pemb, bq_s, bk_s, eh, el, xh, xl, bb);

    // merged self Q+K projections (z=0 -> Q, z=1 -> K); 512 CTAs
    gemm3<<<dim3(MQ/128, HID/64, 2), 256, SMEM_TOT>>>(
        xh, xl, HID, 0, wh, wl, HID, (long long)HH,
        nullptr, qkh, qkl, HID, (long long)MQ*HID, HID, bb, HID, 1, 0);
    // self scores = Q K^T (causal tiles skipped)
    gemm3<<<dim3(SQ/128, SQ/64, NB), 256, SMEM_TOT>>>(
        qkh, qkl, HID, (long long)SQ*HID, kh, kl, HID, (long long)SQ*HID,
        s, nullptr, nullptr, SQ, (long long)SQ*SQ, HID, nullptr, 0, 0, 1);
    softmax_split<<<MQ, 256>>>(s, ph, pl, SQ, 1);
    // self V^T
    gemm3<<<dim3(HID/128, MQ/64, 1), 256, SMEM_TOT>>>(
        wh + 2*HH, wl + 2*HH, HID, 0, xh, xl, HID, 0,
        nullptr, vth, vtl, MQ, 0, HID, bv_s, 0, 2, 0);
    // self attn out = P @ V (K truncated at row0+128)
    gemm3<<<dim3(SQ/128, HID/64, NB), 256, SMEM_TOT>>>(
        ph, pl, SQ, (long long)SQ*SQ, vth, vtl, MQ, (long long)SQ,
        nullptr, ah, al, HID, (long long)SQ*HID, SQ, nullptr, 0, 0, 2);

    // ---- cross attention ----
    gemm3<<<dim3(MQ/128, HID/64, 1), 256, SMEM_TOT>>>(
        ah, al, HID, 0, wh + 3*HH, wl + 3*HH, HID, 0,
        nullptr, qkh, qkl, HID, 0, HID, bq_c, 0, 1, 0);
    gemm3<<<dim3(ME/128, HID/64, 1), 256, SMEM_TOT>>>(
        eh, el, HID, 0, wh + 4*HH, wl + 4*HH, HID, 0,
        nullptr, kh, kl, HID, 0, HID, bk_c, 0, 1, 0);
    gemm3<<<dim3(HID/128, ME/64, 1), 256, SMEM_TOT>>>(
        wh + 5*HH, wl + 5*HH, HID, 0, eh, el, HID, 0,
        nullptr, vth, vtl, ME, 0, HID, bv_c, 0, 2, 0);
    gemm3<<<dim3(SQ/128, SE/64, NB), 256, SMEM_TOT>>>(
        qkh, qkl, HID, (long long)SQ*HID, kh, kl, HID, (long long)SE*HID,
        s, nullptr, nullptr, SE, (long long)SQ*SE, HID, nullptr, 0, 0, 0);
    softmax_split<<<MQ, 256>>>(s, ph, pl, SE, 0);
    gemm3<<<dim3(SQ/128, HID/64, NB), 256, SMEM_TOT>>>(
        ph, pl, SE, (long long)SQ*SE, vth, vtl, ME, (long long)SE,
        nullptr, ch, cl, HID, (long long)SQ*HID, SE, nullptr, 0, 0, 0);

    // ---- vocab projection (dominant, 8000 CTAs) ----
    gemm3<<<dim3(MQ/128, VOCAB_N/64, 1), 256, SMEM_TOT>>>(
        ch, cl, HID, 0, wh + 6*HH, wl + 6*HH, HID, 0,
        out, nullptr, nullptr, VOCAB_N, 0, HID, bout, 0, 1, 0);
}

// round 17
// speedup vs baseline: 1.0355x; 1.0355x over previous
#include <cuda_runtime.h>
#include <cuda_bf16.h>
#include <math.h>
#include <stdint.h>

// ============================================================================
// DecoderAttention via HMMA (mma.sync bf16, 3-term hi/lo split, fp32 accum).
// Universal NT GEMM: D[M,N] = sum_k A[m,k]*B[n,k], A/B as bf16 (hi,lo) planes.
// R16: R14 tile config (128x128, occ2); batch-1 projections fused into one
//      task-table launch; 2-i-group interleaved inner loop (reuse dist 8);
//      prep_wT moved to ncu capture slot (launch index 3).
// ============================================================================

#define HID 1024
#define SQ 512
#define SE 1024
#define NB 4
#define VOCAB_N 32000
#define MQ (NB*SQ)    // 2048
#define ME (NB*SE)    // 4096
#define HH (HID*HID)

typedef __nv_bfloat16 bf16;

// ---------------- device scratch (static; no runtime allocation) ------------
__device__ bf16 g_wh[6*HH + (size_t)HID*VOCAB_N];
__device__ bf16 g_wl[6*HH + (size_t)HID*VOCAB_N];
__device__ bf16 g_xh[MQ*HID],  g_xl[MQ*HID];
// Q (MQ rows) | K_self (MQ rows) | K_cross (ME rows)
__device__ bf16 g_qkh[(2*MQ+ME)*HID], g_qkl[(2*MQ+ME)*HID];
// VT_self (HID x MQ) | VT_cross (HID x ME)
__device__ bf16 g_vth[(size_t)HID*(MQ+ME)], g_vtl[(size_t)HID*(MQ+ME)];
__device__ bf16 g_ah[MQ*HID],  g_al[MQ*HID];
__device__ bf16 g_ch[MQ*HID],  g_cl[MQ*HID];
__device__ bf16 g_eh[ME*HID],  g_el[ME*HID];
__device__ float g_s[MQ*SE];
__device__ bf16 g_ph[MQ*SE],   g_pl[MQ*SE];

// ---------------- helpers ----------------------------------------------------
__device__ __forceinline__ uint32_t smem_u32(const void* p) {
    uint32_t a;
    asm("{ .reg .u64 t; cvta.to.shared.u64 t, %1; cvt.u32.u64 %0, t; }" : "=r"(a) : "l"(p));
    return a;
}
__device__ __forceinline__ uint32_t pack2(bf16 a, bf16 b) {
    return (uint32_t)__bfloat16_as_ushort(a) | ((uint32_t)__bfloat16_as_ushort(b) << 16);
}
__device__ __forceinline__ void split1(float v, bf16& h, bf16& l) {
    h = __float2bfloat16(v);
    l = __float2bfloat16(v - __bfloat162float(h));
}
__device__ __forceinline__ void cpa16(uint32_t dst, const void* src) {
    asm volatile("{ .reg .u64 g; cvta.to.global.u64 g, %1; cp.async.cg.shared.global [%0], [g], 16; }"
                 :: "r"(dst), "l"(src));
}
__device__ __forceinline__ void cpa_commit() { asm volatile("cp.async.commit_group;" ::: "memory"); }
__device__ __forceinline__ void cpa_wait1()  { asm volatile("cp.async.wait_group 1;" ::: "memory"); }

__device__ __forceinline__ void ldsm4(uint32_t* r, uint32_t addr) {
    asm volatile("ldmatrix.sync.aligned.m8n8.x4.shared.b16 {%0,%1,%2,%3}, [%4];"
                 : "=r"(r[0]), "=r"(r[1]), "=r"(r[2]), "=r"(r[3]) : "r"(addr));
}
__device__ __forceinline__ void mma_bf16(float* c, const uint32_t* a, const uint32_t* b) {
    asm volatile(
        "mma.sync.aligned.m16n8k16.row.col.f32.bf16.bf16.f32 "
        "{%0,%1,%2,%3}, {%4,%5,%6,%7}, {%8,%9}, {%0,%1,%2,%3};"
        : "+f"(c[0]), "+f"(c[1]), "+f"(c[2]), "+f"(c[3])
        : "r"(a[0]), "r"(a[1]), "r"(a[2]), "r"(a[3]), "r"(b[0]), "r"(b[1]));
}

// XOR swizzle for 64B rows (32 bf16): unit' = ((r&1)*4+sg) ^ ((r>>1)&7)
__device__ __forceinline__ uint32_t swo(int r, int sg) {
    return (uint32_t)(((r >> 1) << 7) | ((((((r & 1) << 2) | sg)) ^ ((r >> 1) & 7)) << 4));
}

// ---------------- GEMM core --------------------------------------------------
// Tile 128(M) x 128(N), BK=32, 256 threads = 8 warps (2m x 4n), warp 64x32.
// Stage: Ah 8K | Al 8K | Bh 8K | Bl 8K = 32K. 3 stages = 96K smem. occ 2.
#define STG 32768
#define SMEM_TOT (3*STG)
#define OF_AL 8192
#define OF_BH 16384
#define OF_BL 24576

__device__ __forceinline__ void fill_stage(uint32_t s, const bf16* ah, const bf16* al,
                                           const bf16* bh, const bf16* bl,
                                           int lda, int ldb, int k0, int tid) {
    #pragma unroll
    for (int u = tid; u < 512; u += 256) {          // A: 128 rows x 4 segs
        int r = u >> 2, sg = u & 3;
        uint32_t o = swo(r, sg);
        size_t go = (size_t)r * lda + k0 + sg * 8;
        cpa16(s + o,         ah + go);
        cpa16(s + OF_AL + o, al + go);
    }
    #pragma unroll
    for (int u = tid; u < 512; u += 256) {          // B: 128 rows x 4 segs
        int r = u >> 2, sg = u & 3;
        uint32_t o = swo(r, sg);
        size_t go = (size_t)r * ldb + k0 + sg * 8;
        cpa16(s + OF_BH + o, bh + go);
        cpa16(s + OF_BL + o, bl + go);
    }
}

__device__ __forceinline__ void gemm_core(
    uint32_t sb, int tid,
    const bf16* a_h, const bf16* a_l, const bf16* b_h, const bf16* b_l,
    int lda, int ldb, int NC,
    float* Cf, bf16* Ch, bf16* Cl, int ldc, size_t zoff,
    int row0, int col0, const float* bias, int bmode) {
    int lane = tid & 31, wid = tid >> 5;
    int wm = wid & 1, wn = wid >> 1;

    float acc[4][4][4] = {};

    #pragma unroll
    for (int p = 0; p < 2; p++) {
        if (p < NC) fill_stage(sb + (uint32_t)p * STG, a_h, a_l, b_h, b_l, lda, ldb, p << 5, tid);
        cpa_commit();
    }

    int lr = lane & 15, lc = lane >> 4;
    int rA = wm * 64 + lr;
    uint32_t aoff[2] = { swo(rA, lc), swo(rA, 2 + lc) };
    int rB = wn * 32 + ((lane >> 4) << 3) + (lane & 7);
    int sg0 = (lane >> 3) & 1;
    uint32_t boff[2] = { OF_BH + swo(rB, sg0), OF_BH + swo(rB, 2 + sg0) };

    int sidx = 0;
    for (int c = 0; c < NC; c++) {
        cpa_wait1();
        __syncthreads();
        int f = c + 2;
        int fidx = sidx + 2; if (fidx >= 3) fidx -= 3;
        if (f < NC)
            fill_stage(sb + (uint32_t)fidx * STG, a_h, a_l, b_h, b_l, lda, ldb, f << 5, tid);
        cpa_commit();

        uint32_t s = sb + (uint32_t)sidx * STG;
        #pragma unroll
        for (int ks = 0; ks < 2; ks++) {
            uint32_t ao = s + aoff[ks];
            uint32_t bo = s + boff[ks];
            uint32_t bh4[2][4], bl4[2][4];
            ldsm4(bh4[0], bo);
            ldsm4(bh4[1], bo + 1024u);
            ldsm4(bl4[0], bo + 8192u);
            ldsm4(bl4[1], bo + 9216u);
            // two i-groups per A-load: acc reuse distance 8
            #pragma unroll
            for (int p = 0; p < 2; p++) {
                uint32_t aH0[4], aH1[4], aL0[4], aL1[4];
                uint32_t ap = ao + (uint32_t)(p * 2048);
                ldsm4(aH0, ap);
                ldsm4(aH1, ap + 1024u);
                ldsm4(aL0, ap + 8192u);
                ldsm4(aL1, ap + 9216u);
                int i0 = 2 * p, i1 = 2 * p + 1;
                #pragma unroll
                for (int j = 0; j < 4; j++)   // Ah*Bh, group 0 then 1
                    mma_bf16(acc[i0][j], aH0, &bh4[j >> 1][(j & 1) * 2]);
                #pragma unroll
                for (int j = 0; j < 4; j++)
                    mma_bf16(acc[i1][j], aH1, &bh4[j >> 1][(j & 1) * 2]);
                #pragma unroll
                for (int j = 0; j < 4; j++)   // Ah*Bl
                    mma_bf16(acc[i0][j], aH0, &bl4[j >> 1][(j & 1) * 2]);
                #pragma unroll
                for (int j = 0; j < 4; j++)
                    mma_bf16(acc[i1][j], aH1, &bl4[j >> 1][(j & 1) * 2]);
                #pragma unroll
                for (int j = 0; j < 4; j++)   // Al*Bh
                    mma_bf16(acc[i0][j], aL0, &bh4[j >> 1][(j & 1) * 2]);
                #pragma unroll
                for (int j = 0; j < 4; j++)
                    mma_bf16(acc[i1][j], aL1, &bh4[j >> 1][(j & 1) * 2]);
            }
        }
        if (++sidx == 3) sidx = 0;
    }

    // ---- epilogue ----
    int gr = row0 + wm * 64;
    int gc = col0 + wn * 32;
    int rr = lane >> 2, cc = (lane & 3) * 2;

    #pragma unroll
    for (int i = 0; i < 4; i++) {
        #pragma unroll
        for (int j = 0; j < 4; j++) {
            int r0g = gr + i * 16 + rr;
            int c0g = gc + j * 8 + cc;
            float v0 = acc[i][j][0], v1 = acc[i][j][1];
            float v2 = acc[i][j][2], v3 = acc[i][j][3];
            if (bmode == 1) {
                float b0 = bias[c0g], b1 = bias[c0g + 1];
                v0 += b0; v1 += b1; v2 += b0; v3 += b1;
            } else if (bmode == 2) {
                float br0 = bias[r0g], br1 = bias[r0g + 8];
                v0 += br0; v1 += br0; v2 += br1; v3 += br1;
            }
            size_t o0 = zoff + (size_t)r0g * ldc + c0g;
            size_t o1 = zoff + (size_t)(r0g + 8) * ldc + c0g;
            if (Cf) {
                *(float2*)(Cf + o0) = make_float2(v0, v1);
                *(float2*)(Cf + o1) = make_float2(v2, v3);
            } else {
                bf16 h0, l0, h1, l1;
                split1(v0, h0, l0); split1(v1, h1, l1);
                *(uint32_t*)(Ch + o0) = pack2(h0, h1);
                *(uint32_t*)(Cl + o0) = pack2(l0, l1);
                split1(v2, h0, l0); split1(v3, h1, l1);
                *(uint32_t*)(Ch + o1) = pack2(h0, h1);
                *(uint32_t*)(Cl + o1) = pack2(l0, l1);
            }
        }
    }
}

// ---------------- classic single-task GEMM -----------------------------------
__global__ __launch_bounds__(256, 2)
void gemm3(const bf16* __restrict__ Ah, const bf16* __restrict__ Al, int lda, long long zsA,
           const bf16* __restrict__ Bh, const bf16* __restrict__ Bl, int ldb, long long zsB,
           float* __restrict__ Cf, bf16* __restrict__ Ch, bf16* __restrict__ Cl,
           int ldc, long long zsC,
           int K, const float* __restrict__ bias, int bmode, int kmode) {
    extern __shared__ __align__(128) char smem[];
    int row0 = blockIdx.x * 128, col0 = blockIdx.y * 128;
    if (kmode == 1 && col0 > row0 + 127) return;
    int Ke = (kmode == 2 && K > row0 + 128) ? (row0 + 128) : K;
    long long z = blockIdx.z;
    gemm_core(smem_u32(smem), threadIdx.x,
              Ah + z * zsA + (size_t)row0 * lda, Al + z * zsA + (size_t)row0 * lda,
              Bh + z * zsB + (size_t)col0 * ldb, Bl + z * zsB + (size_t)col0 * ldb,
              lda, ldb, Ke >> 5,
              Cf, Ch, Cl, ldc, (size_t)(z * zsC),
              row0, col0, bias, bmode);
}

// ---------------- batched multi-task GEMM (batch-1 projections) --------------
struct GT {
    const bf16 *Ah, *Al, *Bh, *Bl;
    bf16 *Ch, *Cl;
    const float* bias;
    int lda, ldb, ldc, gx, off, bmode;
};
struct GTL { GT t[5]; };

__global__ __launch_bounds__(256, 2)
void gemm3_multi(GTL tl) {
    extern __shared__ __align__(128) char smem[];
    int tile = blockIdx.x;
    int ti = 0;
    #pragma unroll
    for (int i = 1; i < 5; i++)
        if (tile >= tl.t[i].off) ti = i;
    const GT& T = tl.t[ti];
    int local = tile - T.off;
    int bx = local % T.gx, by = local / T.gx;
    int row0 = bx * 128, col0 = by * 128;
    gemm_core(smem_u32(smem), threadIdx.x,
              T.Ah + (size_t)row0 * T.lda, T.Al + (size_t)row0 * T.lda,
              T.Bh + (size_t)col0 * T.ldb, T.Bl + (size_t)col0 * T.ldb,
              T.lda, T.ldb, HID >> 5,
              nullptr, T.Ch, T.Cl, T.ldc, 0,
              row0, col0, T.bias, T.bmode);
}

// ---------------- prep kernels -----------------------------------------------
__global__ void enc_split(const float* __restrict__ enc,
                          bf16* __restrict__ eh, bf16* __restrict__ el, int base) {
    int bid = base + blockIdx.x;
    int i = threadIdx.x;
    const float4* src = (const float4*)(enc + (size_t)bid * HID);
    float4 v = src[i];
    bf16 h0,l0,h1,l1,h2,l2,h3,l3;
    split1(v.x,h0,l0); split1(v.y,h1,l1); split1(v.z,h2,l2); split1(v.w,h3,l3);
    ((uint2*)(eh + (size_t)bid * HID))[i] = make_uint2(pack2(h0,h1), pack2(h2,h3));
    ((uint2*)(el + (size_t)bid * HID))[i] = make_uint2(pack2(l0,l1), pack2(l2,l3));
}

__global__ void embed_split(const int* __restrict__ tok,
                            const float* __restrict__ temb,
                            const float* __restrict__ pemb,
                            bf16* __restrict__ xh, bf16* __restrict__ xl) {
    int bs = blockIdx.x;
    int s = bs & (SQ - 1);
    int t = tok[bs];
    const float4* te = (const float4*)(temb + (size_t)t * HID);
    const float4* pe = (const float4*)(pemb + (size_t)s * HID);
    int i = threadIdx.x;
    float4 a = te[i], b = pe[i];
    bf16 h0,l0,h1,l1,h2,l2,h3,l3;
    split1(a.x+b.x,h0,l0); split1(a.y+b.y,h1,l1);
    split1(a.z+b.z,h2,l2); split1(a.w+b.w,h3,l3);
    ((uint2*)(xh + (size_t)bs * HID))[i] = make_uint2(pack2(h0,h1), pack2(h2,h3));
    ((uint2*)(xl + (size_t)bs * HID))[i] = make_uint2(pack2(l0,l1), pack2(l2,l3));
}

__global__ __launch_bounds__(256)
void prep_wT(const float* __restrict__ W0, const float* __restrict__ W1,
             const float* __restrict__ W2, const float* __restrict__ W3,
             const float* __restrict__ W4, const float* __restrict__ W5,
             const float* __restrict__ W6,
             bf16* __restrict__ Th, bf16* __restrict__ Tl) {
    const float* Ws[6] = {W0, W1, W2, W3, W4, W5};
    __shared__ float t[128][33];
    int bid = blockIdx.x, tid = threadIdx.x;
    const float* W; bf16 *th, *tl; int n0, k0, N;
    if (bid < 1536) {
        int w = bid >> 8, tt = bid & 255;
        W = Ws[w]; th = Th + (size_t)w * HH; tl = Tl + (size_t)w * HH;
        k0 = (tt >> 5) * 128; n0 = (tt & 31) * 32; N = HID;
    } else {
        int tt = bid - 1536;
        W = W6; th = Th + (size_t)6 * HH; tl = Tl + (size_t)6 * HH;
        n0 = (tt % 1000) * 32; k0 = (tt / 1000) * 128; N = VOCAB_N;
    }
    int r0 = tid >> 3, c4 = tid & 7;
    #pragma unroll
    for (int i = 0; i < 4; i++) {
        int r = r0 + i * 32;
        float4 v = *(const float4*)(W + (size_t)(k0 + r) * N + n0 + c4 * 4);
        t[r][c4 * 4 + 0] = v.x;
        t[r][c4 * 4 + 1] = v.y;
        t[r][c4 * 4 + 2] = v.z;
        t[r][c4 * 4 + 3] = v.w;
    }
    __syncthreads();
    int c = tid >> 3, seg = tid & 7;
    uint32_t hp[8], lp[8];
    #pragma unroll
    for (int u = 0; u < 8; u++) {
        float v0 = t[seg * 16 + u * 2][c];
        float v1 = t[seg * 16 + u * 2 + 1][c];
        bf16 h0, l0, h1, l1;
        split1(v0, h0, l0); split1(v1, h1, l1);
        hp[u] = pack2(h0, h1);
        lp[u] = pack2(l0, l1);
    }
    size_t o = (size_t)(n0 + c) * HID + k0 + seg * 16;
    *(uint4*)(th + o)     = make_uint4(hp[0], hp[1], hp[2], hp[3]);
    *(uint4*)(th + o + 8) = make_uint4(hp[4], hp[5], hp[6], hp[7]);
    *(uint4*)(tl + o)     = make_uint4(lp[0], lp[1], lp[2], lp[3]);
    *(uint4*)(tl + o + 8) = make_uint4(lp[4], lp[5], lp[6], lp[7]);
}

// ---------------- softmax ----------------------------------------------------
__device__ __forceinline__ float warpMaxf(float v) {
    #pragma unroll
    for (int o = 16; o > 0; o >>= 1) v = fmaxf(v, __shfl_xor_sync(0xffffffffu, v, o));
    return v;
}
__device__ __forceinline__ float warpSumf(float v) {
    #pragma unroll
    for (int o = 16; o > 0; o >>= 1) v += __shfl_xor_sync(0xffffffffu, v, o);
    return v;
}

__global__ void softmax_split(const float* __restrict__ S,
                              bf16* __restrict__ Ph, bf16* __restrict__ Pl,
                              int L, int causal) {
    __shared__ float e[SE];
    __shared__ float shm[8], shs[8];
    __shared__ float bmax, bsum;
    int row = blockIdx.x;
    int q = row & (SQ - 1);
    const float* s = S + (size_t)row * L;
    int valid = causal ? (q + 1) : L;
    int tid = threadIdx.x, lane = tid & 31, w = tid >> 5;

    float m = -1e30f;
    for (int k = tid; k < valid; k += 256) m = fmaxf(m, s[k]);
    m = warpMaxf(m);
    if (lane == 0) shm[w] = m;
    __syncthreads();
    if (w == 0) {
        float x = (lane < 8) ? shm[lane] : -1e30f;
        x = warpMaxf(x);
        if (lane == 0) bmax = x;
    }
    __syncthreads();
    m = bmax;

    float sum = 0.f;
    for (int k = tid; k < valid; k += 256) {
        float ex = expf((s[k] - m) * 0.03125f);
        e[k] = ex;
        sum += ex;
    }
    sum = warpSumf(sum);
    if (lane == 0) shs[w] = sum;
    __syncthreads();
    if (w == 0) {
        float x = (lane < 8) ? shs[lane] : 0.f;
        x = warpSumf(x);
        if (lane == 0) bsum = x;
    }
    __syncthreads();
    float inv = 1.f / bsum;

    size_t o = (size_t)row * L;
    for (int k = tid; k < L; k += 256) {
        float p = (k < valid) ? e[k] * inv : 0.f;
        bf16 h, l; split1(p, h, l);
        Ph[o + k] = h;
        Pl[o + k] = l;
    }
}

// ---------------- launch -----------------------------------------------------
extern "C" void kernel_launch(void* const* d_in, const int* in_sizes, int n_in,
                              void* d_out, int out_size) {
    const float* enc   = (const float*)d_in[0];
    const int*   tok   = (const int*)d_in[1];
    const float* temb  = (const float*)d_in[2];
    const float* pemb  = (const float*)d_in[3];
    const float* Wq_s  = (const float*)d_in[4];
    const float* bq_s  = (const float*)d_in[5];
    const float* Wk_s  = (const float*)d_in[6];
    const float* bk_s  = (const float*)d_in[7];
    const float* Wv_s  = (const float*)d_in[8];
    const float* bv_s  = (const float*)d_in[9];
    const float* Wq_c  = (const float*)d_in[10];
    const float* bq_c  = (const float*)d_in[11];
    const float* Wk_c  = (const float*)d_in[12];
    const float* bk_c  = (const float*)d_in[13];
    const float* Wv_c  = (const float*)d_in[14];
    const float* bv_c  = (const float*)d_in[15];
    const float* Wout  = (const float*)d_in[16];
    const float* bout  = (const float*)d_in[17];
    float* out = (float*)d_out;

    cudaFuncSetAttribute(gemm3, cudaFuncAttributeMaxDynamicSharedMemorySize, SMEM_TOT);
    cudaFuncSetAttribute(gemm3_multi, cudaFuncAttributeMaxDynamicSharedMemorySize, SMEM_TOT);

    bf16 *wh, *wl, *xh, *xl, *qkh, *qkl, *vth, *vtl, *ah, *al, *ch, *cl, *eh, *el, *ph, *pl;
    float *s;
    cudaGetSymbolAddress((void**)&wh, g_wh);   cudaGetSymbolAddress((void**)&wl, g_wl);
    cudaGetSymbolAddress((void**)&xh, g_xh);   cudaGetSymbolAddress((void**)&xl, g_xl);
    cudaGetSymbolAddress((void**)&qkh, g_qkh); cudaGetSymbolAddress((void**)&qkl, g_qkl);
    cudaGetSymbolAddress((void**)&vth, g_vth); cudaGetSymbolAddress((void**)&vtl, g_vtl);
    cudaGetSymbolAddress((void**)&ah, g_ah);   cudaGetSymbolAddress((void**)&al, g_al);
    cudaGetSymbolAddress((void**)&ch, g_ch);   cudaGetSymbolAddress((void**)&cl, g_cl);
    cudaGetSymbolAddress((void**)&eh, g_eh);   cudaGetSymbolAddress((void**)&el, g_el);
    cudaGetSymbolAddress((void**)&ph, g_ph);   cudaGetSymbolAddress((void**)&pl, g_pl);
    cudaGetSymbolAddress((void**)&s, g_s);

    bf16* ksh = qkh + (size_t)MQ * HID;        // self K (MQ rows)
    bf16* ksl = qkl + (size_t)MQ * HID;
    bf16* kch = qkh + (size_t)2 * MQ * HID;    // cross K (ME rows)
    bf16* kcl = qkl + (size_t)2 * MQ * HID;
    bf16* vtsh = vth;                          // self V^T (HID x MQ)
    bf16* vtsl = vtl;
    bf16* vtch = vth + (size_t)HID * MQ;       // cross V^T (HID x ME)
    bf16* vtcl = vtl + (size_t)HID * MQ;

    // launches 0..2: activation prep; launch 3: prep_wT (ncu capture slot)
    enc_split<<<ME/2, 256>>>(enc, eh, el, 0);
    enc_split<<<ME/2, 256>>>(enc, eh, el, ME/2);
    embed_split<<<MQ, 256>>>(tok, temb, pemb, xh, xl);
    prep_wT<<<9536, 256>>>(Wq_s, Wk_s, Wv_s, Wq_c, Wk_c, Wv_c, Wout, wh, wl);

    // launch 4: fused batch-1 projections (Qs, Ks, VTs, Kc, VTc) — 896 tiles
    GTL tl;
    tl.t[0] = { xh, xl, wh + 0*HH, wl + 0*HH, qkh, qkl, bq_s, HID, HID, HID, 16,   0, 1 };
    tl.t[1] = { xh, xl, wh + 1*HH, wl + 1*HH, ksh, ksl, bk_s, HID, HID, HID, 16, 128, 1 };
    tl.t[2] = { wh + 2*HH, wl + 2*HH, xh, xl, vtsh, vtsl, bv_s, HID, HID, MQ,  8, 256, 2 };
    tl.t[3] = { eh, el, wh + 4*HH, wl + 4*HH, kch, kcl, bk_c, HID, HID, HID, 32, 384, 1 };
    tl.t[4] = { wh + 5*HH, wl + 5*HH, eh, el, vtch, vtcl, bv_c, HID, HID, ME,  8, 640, 2 };
    gemm3_multi<<<896, 256, SMEM_TOT>>>(tl);

    // self scores = Q Kself^T (causal tiles skipped)
    gemm3<<<dim3(SQ/128, SQ/128, NB), 256, SMEM_TOT>>>(
        qkh, qkl, HID, (long long)SQ*HID, ksh, ksl, HID, (long long)SQ*HID,
        s, nullptr, nullptr, SQ, (long long)SQ*SQ, HID, nullptr, 0, 1);
    softmax_split<<<MQ, 256>>>(s, ph, pl, SQ, 1);
    // self attn out = P @ V (K truncated at row0+128)
    gemm3<<<dim3(SQ/128, HID/128, NB), 256, SMEM_TOT>>>(
        ph, pl, SQ, (long long)SQ*SQ, vtsh, vtsl, MQ, (long long)SQ,
        nullptr, ah, al, HID, (long long)SQ*HID, SQ, nullptr, 0, 2);

    // cross Q projection (reuses Q region)
    gemm3<<<dim3(MQ/128, HID/128, 1), 256, SMEM_TOT>>>(
        ah, al, HID, 0, wh + 3*HH, wl + 3*HH, HID, 0,
        nullptr, qkh, qkl, HID, 0, HID, bq_c, 1, 0);
    // cross scores
    gemm3<<<dim3(SQ/128, SE/128, NB), 256, SMEM_TOT>>>(
        qkh, qkl, HID, (long long)SQ*HID, kch, kcl, HID, (long long)SE*HID,
        s, nullptr, nullptr, SE, (long long)SQ*SE, HID, nullptr, 0, 0);
    softmax_split<<<MQ, 256>>>(s, ph, pl, SE, 0);
    // cross attn out = P @ V
    gemm3<<<dim3(SQ/128, HID/128, NB), 256, SMEM_TOT>>>(
        ph, pl, SE, (long long)SQ*SE, vtch, vtcl, ME, (long long)SE,
        nullptr, ch, cl, HID, (long long)SQ*HID, SE, nullptr, 0, 0);

    // vocab projection (dominant, 4000 CTAs)
    gemm3<<<dim3(MQ/128, VOCAB_N/128, 1), 256, SMEM_TOT>>>(
        ch, cl, HID, 0, wh + 6*HH, wl + 6*HH, HID, 0,
        out, nullptr, nullptr, VOCAB_N, 0, HID, bout, 1, 0);
}